// round 2
// baseline (speedup 1.0000x reference)
#include <cuda_runtime.h>
#include <cuda_bf16.h>

#define NUM_G 32768

// Scratch (allocation-free: __device__ globals)
__device__ float  g_tsum[NUM_G];
__device__ float  g_psum[NUM_G];
__device__ int    g_count[NUM_G];
__device__ float2 g_pack[NUM_G];   // {w = valid ? 1/tsum : 0,  lse = log(psum)}
__device__ float  g_total;
__device__ int    g_nvalid;

// Pure-FMA exp: exp(x) = 2^(x*log2e). Magic-number round, deg-5 poly on [-0.5,0.5].
// Rel err ~2e-6; avoids the MUFU.EX2 throughput wall (8M exps would cost ~60us on MUFU).
__device__ __forceinline__ float fexp(float x) {
    const float L2E = 1.4426950408889634f;
    float z  = fmaf(x, L2E, 12582912.0f);           // 1.5*2^23 magic
    int   n  = __float_as_int(z) - 0x4B400000;      // round(x*log2e) as int
    float zi = z - 12582912.0f;                     // round(x*log2e) as float
    float f  = fmaf(x, L2E, -zi);                   // frac in [-0.5, 0.5]
    float p  = 1.3333558146e-3f;
    p = fmaf(p, f, 9.6181291076e-3f);
    p = fmaf(p, f, 5.5504108664e-2f);
    p = fmaf(p, f, 2.4022650696e-1f);
    p = fmaf(p, f, 6.9314718056e-1f);
    p = fmaf(p, f, 1.0f);
    return __int_as_float(__float_as_int(p) + (n << 23));
}

__global__ void k_zero() {
    int i = blockIdx.x * blockDim.x + threadIdx.x;
    if (i < NUM_G) {
        g_tsum[i] = 0.0f;
        g_psum[i] = 0.0f;
        g_count[i] = 0;
    }
    if (i == 0) { g_total = 0.0f; g_nvalid = 0; }
}

// Pass 1: segment sums of exp(t), exp(p), and counts.
__global__ void k_accum(const float4* __restrict__ p4,
                        const float4* __restrict__ t4,
                        const int4*  __restrict__ g4, int nv) {
    int i = blockIdx.x * blockDim.x + threadIdx.x;
    if (i >= nv) return;
    float4 p = p4[i];
    float4 t = t4[i];
    int4   g = g4[i];
    atomicAdd(&g_tsum[g.x], fexp(t.x));
    atomicAdd(&g_psum[g.x], fexp(p.x));
    atomicAdd(&g_count[g.x], 1);
    atomicAdd(&g_tsum[g.y], fexp(t.y));
    atomicAdd(&g_psum[g.y], fexp(p.y));
    atomicAdd(&g_count[g.y], 1);
    atomicAdd(&g_tsum[g.z], fexp(t.z));
    atomicAdd(&g_psum[g.z], fexp(p.z));
    atomicAdd(&g_count[g.z], 1);
    atomicAdd(&g_tsum[g.w], fexp(t.w));
    atomicAdd(&g_psum[g.w], fexp(p.w));
    atomicAdd(&g_count[g.w], 1);
}

// Per-group finalize: pack (1/tsum or 0, log(psum)); count valid groups.
__global__ void k_group() {
    int g = blockIdx.x * blockDim.x + threadIdx.x;
    if (g >= NUM_G) return;
    int   c  = g_count[g];
    float ts = g_tsum[g];
    float ps = g_psum[g];
    bool valid = (c >= 2);
    float w   = valid ? (1.0f / ts) : 0.0f;
    float lse = (c > 0) ? logf(ps) : 0.0f;   // guard -inf for empty groups
    g_pack[g] = make_float2(w, lse);
    unsigned b = __ballot_sync(0xffffffffu, valid);
    if ((threadIdx.x & 31) == 0) atomicAdd(&g_nvalid, __popc(b));
}

// Pass 2: loss = -sum_i  (exp(t_i) * w[g]) * (p_i - lse[g])   over valid groups.
__global__ void k_loss(const float4* __restrict__ p4,
                       const float4* __restrict__ t4,
                       const int4*  __restrict__ g4, int nv) {
    int i = blockIdx.x * blockDim.x + threadIdx.x;
    float s = 0.0f;
    if (i < nv) {
        float4 p = p4[i];
        float4 t = t4[i];
        int4   g = g4[i];
        float2 a;
        a = g_pack[g.x];  s = fmaf(fexp(t.x) * a.x, p.x - a.y, s);
        a = g_pack[g.y];  s = fmaf(fexp(t.y) * a.x, p.y - a.y, s);
        a = g_pack[g.z];  s = fmaf(fexp(t.z) * a.x, p.z - a.y, s);
        a = g_pack[g.w];  s = fmaf(fexp(t.w) * a.x, p.w - a.y, s);
    }
    // warp reduce
    #pragma unroll
    for (int o = 16; o > 0; o >>= 1) s += __shfl_down_sync(0xffffffffu, s, o);
    __shared__ float sh[8];
    int lane = threadIdx.x & 31, wid = threadIdx.x >> 5;
    if (lane == 0) sh[wid] = s;
    __syncthreads();
    if (wid == 0) {
        s = (lane < (blockDim.x >> 5)) ? sh[lane] : 0.0f;
        #pragma unroll
        for (int o = 4; o > 0; o >>= 1) s += __shfl_down_sync(0xffffffffu, s, o);
        if (lane == 0) atomicAdd(&g_total, -s);
    }
}

__global__ void k_final(float* out) {
    int nv = g_nvalid;
    out[0] = (nv > 0) ? (g_total / (float)nv) : 0.0f;
}

extern "C" void kernel_launch(void* const* d_in, const int* in_sizes, int n_in,
                              void* d_out, int out_size) {
    const float* pred = (const float*)d_in[0];
    const float* targ = (const float*)d_in[1];
    const int*   gid  = (const int*)d_in[2];
    float* out = (float*)d_out;
    int n  = in_sizes[0];
    int nv = n / 4;                    // n is a multiple of 4 (4,194,304)
    int gb = (nv + 255) / 256;

    k_zero<<<(NUM_G + 255) / 256, 256>>>();
    k_accum<<<gb, 256>>>((const float4*)pred, (const float4*)targ, (const int4*)gid, nv);
    k_group<<<(NUM_G + 255) / 256, 256>>>();
    k_loss<<<gb, 256>>>((const float4*)pred, (const float4*)targ, (const int4*)gid, nv);
    k_final<<<1, 1>>>(out);
}

// round 3
// speedup vs baseline: 1.8968x; 1.8968x over previous
#include <cuda_runtime.h>
#include <cuda_bf16.h>

#define NUM_G 32768

// Scratch (allocation-free: __device__ globals)
__device__ float4 g_acc[NUM_G];    // {tsum, psum, count, pad}
__device__ float2 g_pack[NUM_G];   // {w = valid ? 1/tsum : 0,  lse = log(psum)}
__device__ float  g_total;
__device__ int    g_nvalid;

// Pure-FMA exp: exp(x) = 2^(x*log2e). Magic-number round, deg-5 poly on [-0.5,0.5].
// Rel err ~2e-6; avoids the MUFU.EX2 throughput wall.
__device__ __forceinline__ float fexp(float x) {
    const float L2E = 1.4426950408889634f;
    float z  = fmaf(x, L2E, 12582912.0f);           // 1.5*2^23 magic
    int   n  = __float_as_int(z) - 0x4B400000;      // round(x*log2e) as int
    float zi = z - 12582912.0f;                     // round(x*log2e) as float
    float f  = fmaf(x, L2E, -zi);                   // frac in [-0.5, 0.5]
    float p  = 1.3333558146e-3f;
    p = fmaf(p, f, 9.6181291076e-3f);
    p = fmaf(p, f, 5.5504108664e-2f);
    p = fmaf(p, f, 2.4022650696e-1f);
    p = fmaf(p, f, 6.9314718056e-1f);
    p = fmaf(p, f, 1.0f);
    return __int_as_float(__float_as_int(p) + (n << 23));
}

// One 16-byte vectorized L2 reduction: {tsum += te, psum += pe, count += 1, pad += 0}
__device__ __forceinline__ void red4(float4* a, float te, float pe) {
    asm volatile("red.global.add.v4.f32 [%0], {%1, %2, %3, %4};"
                 :: "l"(a), "f"(te), "f"(pe), "f"(1.0f), "f"(0.0f) : "memory");
}

__global__ void k_zero() {
    int i = blockIdx.x * blockDim.x + threadIdx.x;
    if (i < NUM_G) g_acc[i] = make_float4(0.f, 0.f, 0.f, 0.f);
    if (i == 0) { g_total = 0.0f; g_nvalid = 0; }
}

// Pass 1: segment sums of exp(t), exp(p), and counts — ONE red.v4 per element.
__global__ void k_accum(const float4* __restrict__ p4,
                        const float4* __restrict__ t4,
                        const int4*  __restrict__ g4, int nv) {
    int i = blockIdx.x * blockDim.x + threadIdx.x;
    if (i >= nv) return;
    float4 p = p4[i];
    float4 t = t4[i];
    int4   g = g4[i];
    red4(&g_acc[g.x], fexp(t.x), fexp(p.x));
    red4(&g_acc[g.y], fexp(t.y), fexp(p.y));
    red4(&g_acc[g.z], fexp(t.z), fexp(p.z));
    red4(&g_acc[g.w], fexp(t.w), fexp(p.w));
}

// Per-group finalize: pack (1/tsum or 0, log(psum)); count valid groups.
__global__ void k_group() {
    int g = blockIdx.x * blockDim.x + threadIdx.x;
    if (g >= NUM_G) return;
    float4 a = g_acc[g];
    int   c  = (int)a.z;
    bool valid = (c >= 2);
    float w   = valid ? (1.0f / a.x) : 0.0f;
    float lse = (c > 0) ? logf(a.y) : 0.0f;   // guard -inf for empty groups
    g_pack[g] = make_float2(w, lse);
    unsigned b = __ballot_sync(0xffffffffu, valid);
    if ((threadIdx.x & 31) == 0) atomicAdd(&g_nvalid, __popc(b));
}

// Pass 2: loss = -sum_i (exp(t_i) * w[g]) * (p_i - lse[g]).
// Each thread handles TWO float4 chunks (i, i+half) for 2x memory-level parallelism.
__global__ void k_loss(const float4* __restrict__ p4,
                       const float4* __restrict__ t4,
                       const int4*  __restrict__ g4, int nv) {
    int half = nv >> 1;
    int i = blockIdx.x * blockDim.x + threadIdx.x;
    float s = 0.0f;
    if (i < half) {
        // Issue all streaming loads + gathers up front (independent).
        float4 pA = p4[i],        pB = p4[i + half];
        float4 tA = t4[i],        tB = t4[i + half];
        int4   gA = g4[i],        gB = g4[i + half];
        float2 ax = __ldg(&g_pack[gA.x]);
        float2 ay = __ldg(&g_pack[gA.y]);
        float2 az = __ldg(&g_pack[gA.z]);
        float2 aw = __ldg(&g_pack[gA.w]);
        float2 bx = __ldg(&g_pack[gB.x]);
        float2 by = __ldg(&g_pack[gB.y]);
        float2 bz = __ldg(&g_pack[gB.z]);
        float2 bw = __ldg(&g_pack[gB.w]);
        s = fmaf(fexp(tA.x) * ax.x, pA.x - ax.y, s);
        s = fmaf(fexp(tA.y) * ay.x, pA.y - ay.y, s);
        s = fmaf(fexp(tA.z) * az.x, pA.z - az.y, s);
        s = fmaf(fexp(tA.w) * aw.x, pA.w - aw.y, s);
        s = fmaf(fexp(tB.x) * bx.x, pB.x - bx.y, s);
        s = fmaf(fexp(tB.y) * by.x, pB.y - by.y, s);
        s = fmaf(fexp(tB.z) * bz.x, pB.z - bz.y, s);
        s = fmaf(fexp(tB.w) * bw.x, pB.w - bw.y, s);
    }
    // warp reduce
    #pragma unroll
    for (int o = 16; o > 0; o >>= 1) s += __shfl_down_sync(0xffffffffu, s, o);
    __shared__ float sh[8];
    int lane = threadIdx.x & 31, wid = threadIdx.x >> 5;
    if (lane == 0) sh[wid] = s;
    __syncthreads();
    if (wid == 0) {
        s = (lane < (blockDim.x >> 5)) ? sh[lane] : 0.0f;
        #pragma unroll
        for (int o = 4; o > 0; o >>= 1) s += __shfl_down_sync(0xffffffffu, s, o);
        if (lane == 0) atomicAdd(&g_total, -s);
    }
}

__global__ void k_final(float* out) {
    int nv = g_nvalid;
    out[0] = (nv > 0) ? (g_total / (float)nv) : 0.0f;
}

extern "C" void kernel_launch(void* const* d_in, const int* in_sizes, int n_in,
                              void* d_out, int out_size) {
    const float* pred = (const float*)d_in[0];
    const float* targ = (const float*)d_in[1];
    const int*   gid  = (const int*)d_in[2];
    float* out = (float*)d_out;
    int n  = in_sizes[0];
    int nv = n / 4;                    // n is a multiple of 4 (4,194,304)
    int gb_accum = (nv + 255) / 256;
    int gb_loss  = (nv / 2 + 255) / 256;

    k_zero<<<(NUM_G + 255) / 256, 256>>>();
    k_accum<<<gb_accum, 256>>>((const float4*)pred, (const float4*)targ, (const int4*)gid, nv);
    k_group<<<(NUM_G + 255) / 256, 256>>>();
    k_loss<<<gb_loss, 256>>>((const float4*)pred, (const float4*)targ, (const int4*)gid, nv);
    k_final<<<1, 1>>>(out);
}

// round 4
// speedup vs baseline: 1.9072x; 1.0055x over previous
#include <cuda_runtime.h>
#include <cuda_bf16.h>

#define NUM_G 32768

// Scratch (allocation-free: __device__ globals)
__device__ float4 g_acc[NUM_G];    // {tsum, psum, S = sum exp(t)*p, count}
__device__ float  g_total;
__device__ int    g_nvalid;

// Pure-FMA exp: exp(x) = 2^(x*log2e). Magic-number round, deg-5 poly on [-0.5,0.5].
// Rel err ~2e-6; avoids the MUFU.EX2 throughput wall.
__device__ __forceinline__ float fexp(float x) {
    const float L2E = 1.4426950408889634f;
    float z  = fmaf(x, L2E, 12582912.0f);           // 1.5*2^23 magic
    int   n  = __float_as_int(z) - 0x4B400000;      // round(x*log2e) as int
    float zi = z - 12582912.0f;                     // round(x*log2e) as float
    float f  = fmaf(x, L2E, -zi);                   // frac in [-0.5, 0.5]
    float p  = 1.3333558146e-3f;
    p = fmaf(p, f, 9.6181291076e-3f);
    p = fmaf(p, f, 5.5504108664e-2f);
    p = fmaf(p, f, 2.4022650696e-1f);
    p = fmaf(p, f, 6.9314718056e-1f);
    p = fmaf(p, f, 1.0f);
    return __int_as_float(__float_as_int(p) + (n << 23));
}

// One 16-byte vectorized L2 reduction: {tsum += te, psum += pe, S += te*p, count += 1}
__device__ __forceinline__ void red4(float4* a, float te, float pe, float s) {
    asm volatile("red.global.add.v4.f32 [%0], {%1, %2, %3, %4};"
                 :: "l"(a), "f"(te), "f"(pe), "f"(s), "f"(1.0f) : "memory");
}

__global__ void k_zero() {
    int i = blockIdx.x * blockDim.x + threadIdx.x;
    if (i < NUM_G) g_acc[i] = make_float4(0.f, 0.f, 0.f, 0.f);
    if (i == 0) { g_total = 0.0f; g_nvalid = 0; }
}

// Single data pass: per-group sums of exp(t), exp(p), exp(t)*p, count.
// ONE red.v4 per element — everything needed for the loss.
__global__ void k_accum(const float4* __restrict__ p4,
                        const float4* __restrict__ t4,
                        const int4*  __restrict__ g4, int nv) {
    int i = blockIdx.x * blockDim.x + threadIdx.x;
    if (i >= nv) return;
    float4 p = p4[i];
    float4 t = t4[i];
    int4   g = g4[i];
    float tex = fexp(t.x), tey = fexp(t.y), tez = fexp(t.z), tew = fexp(t.w);
    red4(&g_acc[g.x], tex, fexp(p.x), tex * p.x);
    red4(&g_acc[g.y], tey, fexp(p.y), tey * p.y);
    red4(&g_acc[g.z], tez, fexp(p.z), tez * p.z);
    red4(&g_acc[g.w], tew, fexp(p.w), tew * p.w);
}

// Per-group finalize + global reduce:
//   loss_g = log(psum_g) - S_g / tsum_g   (valid iff count >= 2)
__global__ void k_group() {
    int g = blockIdx.x * blockDim.x + threadIdx.x;
    float s = 0.0f;
    bool valid = false;
    if (g < NUM_G) {
        float4 a = g_acc[g];
        valid = (a.w >= 1.5f);          // count >= 2
        if (valid) s = logf(a.y) - a.z / a.x;
    }
    // warp reduce loss + valid count
    unsigned b = __ballot_sync(0xffffffffu, valid);
    #pragma unroll
    for (int o = 16; o > 0; o >>= 1) s += __shfl_down_sync(0xffffffffu, s, o);
    __shared__ float sh[8];
    __shared__ int   shc[8];
    int lane = threadIdx.x & 31, wid = threadIdx.x >> 5;
    if (lane == 0) { sh[wid] = s; shc[wid] = __popc(b); }
    __syncthreads();
    if (wid == 0) {
        s = (lane < (blockDim.x >> 5)) ? sh[lane] : 0.0f;
        int c = (lane < (blockDim.x >> 5)) ? shc[lane] : 0;
        #pragma unroll
        for (int o = 4; o > 0; o >>= 1) {
            s += __shfl_down_sync(0xffffffffu, s, o);
            c += __shfl_down_sync(0xffffffffu, c, o);
        }
        if (lane == 0) {
            atomicAdd(&g_total, s);
            atomicAdd(&g_nvalid, c);
        }
    }
}

__global__ void k_final(float* out) {
    int nv = g_nvalid;
    out[0] = (nv > 0) ? (g_total / (float)nv) : 0.0f;
}

extern "C" void kernel_launch(void* const* d_in, const int* in_sizes, int n_in,
                              void* d_out, int out_size) {
    const float* pred = (const float*)d_in[0];
    const float* targ = (const float*)d_in[1];
    const int*   gid  = (const int*)d_in[2];
    float* out = (float*)d_out;
    int n  = in_sizes[0];
    int nv = n / 4;                    // n is a multiple of 4 (4,194,304)
    int gb = (nv + 255) / 256;

    k_zero<<<(NUM_G + 255) / 256, 256>>>();
    k_accum<<<gb, 256>>>((const float4*)pred, (const float4*)targ, (const int4*)gid, nv);
    k_group<<<(NUM_G + 255) / 256, 256>>>();
    k_final<<<1, 1>>>(out);
}

// round 5
// speedup vs baseline: 2.6454x; 1.3870x over previous
#include <cuda_runtime.h>
#include <cuda_bf16.h>

#define NUM_G 32768

// Scratch (allocation-free __device__ globals; zero-initialized at load).
// INVARIANT: all scratch is zero at kernel_launch entry; k_group_final
// restores it to zero, so every graph replay sees the same state.
__device__ float4   g_acc[NUM_G];   // {tsum, psum, S = sum exp(t)*p, count}
__device__ float    g_total;
__device__ int      g_nvalid;
__device__ unsigned g_done;

// Pure-FMA exp: exp(x) = 2^(x*log2e). Magic-number round, deg-5 poly on [-0.5,0.5].
// Rel err ~2e-6; avoids the MUFU.EX2 throughput wall.
__device__ __forceinline__ float fexp(float x) {
    const float L2E = 1.4426950408889634f;
    float z  = fmaf(x, L2E, 12582912.0f);           // 1.5*2^23 magic
    int   n  = __float_as_int(z) - 0x4B400000;      // round(x*log2e) as int
    float zi = z - 12582912.0f;                     // round(x*log2e) as float
    float f  = fmaf(x, L2E, -zi);                   // frac in [-0.5, 0.5]
    float p  = 1.3333558146e-3f;
    p = fmaf(p, f, 9.6181291076e-3f);
    p = fmaf(p, f, 5.5504108664e-2f);
    p = fmaf(p, f, 2.4022650696e-1f);
    p = fmaf(p, f, 6.9314718056e-1f);
    p = fmaf(p, f, 1.0f);
    return __int_as_float(__float_as_int(p) + (n << 23));
}

// One 16-byte vectorized L2 reduction: {tsum += te, psum += pe, S += te*p, count += 1}
__device__ __forceinline__ void red4(float4* a, float te, float pe, float s) {
    asm volatile("red.global.add.v4.f32 [%0], {%1, %2, %3, %4};"
                 :: "l"(a), "f"(te), "f"(pe), "f"(s), "f"(1.0f) : "memory");
}

// Single data pass: per-group sums of exp(t), exp(p), exp(t)*p, count.
// ONE red.v4 per element. Two float4 chunks per thread for issue efficiency.
__global__ void k_accum(const float4* __restrict__ p4,
                        const float4* __restrict__ t4,
                        const int4*  __restrict__ g4, int nv) {
    int half = nv >> 1;
    int i = blockIdx.x * blockDim.x + threadIdx.x;
    if (i >= half) return;
    float4 pA = p4[i], pB = p4[i + half];
    float4 tA = t4[i], tB = t4[i + half];
    int4   gA = g4[i], gB = g4[i + half];

    float ax = fexp(tA.x), ay = fexp(tA.y), az = fexp(tA.z), aw = fexp(tA.w);
    float bx = fexp(tB.x), by = fexp(tB.y), bz = fexp(tB.z), bw = fexp(tB.w);

    red4(&g_acc[gA.x], ax, fexp(pA.x), ax * pA.x);
    red4(&g_acc[gA.y], ay, fexp(pA.y), ay * pA.y);
    red4(&g_acc[gA.z], az, fexp(pA.z), az * pA.z);
    red4(&g_acc[gA.w], aw, fexp(pA.w), aw * pA.w);
    red4(&g_acc[gB.x], bx, fexp(pB.x), bx * pB.x);
    red4(&g_acc[gB.y], by, fexp(pB.y), by * pB.y);
    red4(&g_acc[gB.z], bz, fexp(pB.z), bz * pB.z);
    red4(&g_acc[gB.w], bw, fexp(pB.w), bw * pB.w);
}

// Finalize: loss_g = log(psum_g) - S_g / tsum_g (valid iff count >= 2),
// global reduce via atomics, last block writes output and resets all scratch.
__global__ void k_group_final(float* out) {
    int g = blockIdx.x * blockDim.x + threadIdx.x;
    float s = 0.0f;
    bool valid = false;
    if (g < NUM_G) {
        float4 a = g_acc[g];
        g_acc[g] = make_float4(0.f, 0.f, 0.f, 0.f);   // restore zero for next replay
        valid = (a.w >= 1.5f);                        // count >= 2
        if (valid) s = logf(a.y) - a.z / a.x;
    }
    // block reduce (loss, valid-count)
    unsigned b = __ballot_sync(0xffffffffu, valid);
    #pragma unroll
    for (int o = 16; o > 0; o >>= 1) s += __shfl_down_sync(0xffffffffu, s, o);
    __shared__ float sh[8];
    __shared__ int   shc[8];
    int lane = threadIdx.x & 31, wid = threadIdx.x >> 5;
    if (lane == 0) { sh[wid] = s; shc[wid] = __popc(b); }
    __syncthreads();
    if (wid == 0) {
        s = (lane < (blockDim.x >> 5)) ? sh[lane] : 0.0f;
        int c = (lane < (blockDim.x >> 5)) ? shc[lane] : 0;
        #pragma unroll
        for (int o = 4; o > 0; o >>= 1) {
            s += __shfl_down_sync(0xffffffffu, s, o);
            c += __shfl_down_sync(0xffffffffu, c, o);
        }
        if (lane == 0) {
            atomicAdd(&g_total, s);
            atomicAdd(&g_nvalid, c);
            __threadfence();
            unsigned ticket = atomicAdd(&g_done, 1u);
            if (ticket == gridDim.x - 1) {
                int   nv = *(volatile int*)&g_nvalid;
                float tt = *(volatile float*)&g_total;
                out[0] = (nv > 0) ? (tt / (float)nv) : 0.0f;
                g_total = 0.0f; g_nvalid = 0; g_done = 0;  // reset for next replay
            }
        }
    }
}

extern "C" void kernel_launch(void* const* d_in, const int* in_sizes, int n_in,
                              void* d_out, int out_size) {
    const float* pred = (const float*)d_in[0];
    const float* targ = (const float*)d_in[1];
    const int*   gid  = (const int*)d_in[2];
    float* out = (float*)d_out;
    int n  = in_sizes[0];
    int nv = n / 4;                    // n is a multiple of 4 (4,194,304)
    int gb = (nv / 2 + 255) / 256;

    k_accum<<<gb, 256>>>((const float4*)pred, (const float4*)targ, (const int4*)gid, nv);
    k_group_final<<<(NUM_G + 255) / 256, 256>>>(out);
}